// round 15
// baseline (speedup 1.0000x reference)
#include <cuda_runtime.h>
#include <cuda_bf16.h>
#include <cstdint>

// Problem constants
#define B_  16
#define S_  64
#define N_  196
#define H_  1024
#define F_  2048
#define E_  512

#define BS_ (B_ * S_)           // 1024
#define BN_ (B_ * N_)           // 3136 = 49*64
#define ATTN_ELEMS (BS_ * F_)   // attn_feats first in d_out

#define KSPLIT 4                // Uv split-K factor (2048/4 = 512)
#define KSPLIT_WH 2             // Wh split-K factor (1024/2 = 512)

// Scratch (__device__ globals; allocation-free rule)
__device__ float g_Wh[BS_ * E_];                 // reduced Wh
__device__ float g_Uv[BN_ * E_];                 // reduced Uv (compact rows)
__device__ float g_UvP[KSPLIT][BN_ * E_];        // Uv split-K partials
__device__ float g_WhP[KSPLIT_WH][BS_ * E_];     // Wh split-K partials
__device__ float g_wu_c[F_ * E_];                // tf32-rounded w_u
__device__ float g_wh_c[H_ * E_];                // tf32-rounded w_h
__device__ float g_wts_c[BS_ * N_];              // tf32-rounded weights
__device__ int   g_row_list[BN_];                // compact idx -> global row
__device__ int   g_idx_map[BN_];                 // global row -> compact idx / -1
__device__ int   g_nact;                         // total active rows
__device__ int   g_ctr_uv[196];                  // per-Uv-tile split arrival counters
__device__ int   g_ctr_wh[64];                   // per-Wh-tile split arrival counters

#define BK 16
#define PA 20    // A smem row stride: frag banks conflict-free
#define PB 132   // B smem row stride: frag banks conflict-free
#define STG 4    // pipeline stages (r7/r12-proven)

__device__ __forceinline__ uint32_t f2tf32(float f) {
    uint32_t u;
    asm("cvt.rna.tf32.f32 %0, %1;" : "=r"(u) : "f"(f));
    return u;
}

__device__ __forceinline__ void mma_tf32(float* c, const uint32_t* a, const uint32_t* b) {
    asm volatile(
        "mma.sync.aligned.m16n8k8.row.col.f32.tf32.tf32.f32 "
        "{%0,%1,%2,%3}, {%4,%5,%6,%7}, {%8,%9}, {%0,%1,%2,%3};"
        : "+f"(c[0]), "+f"(c[1]), "+f"(c[2]), "+f"(c[3])
        : "r"(a[0]), "r"(a[1]), "r"(a[2]), "r"(a[3]), "r"(b[0]), "r"(b[1]));
}

__device__ __forceinline__ void cp_async16(uint32_t smem, const void* gmem, bool pred) {
    int sz = pred ? 16 : 0;
    asm volatile("cp.async.cg.shared.global [%0], [%1], 16, %2;"
                 :: "r"(smem), "l"(gmem), "r"(sz));
}

// ---------------------------------------------------------------------------
// Fused prep kernel: blocks [0,384) tf32-round w_u|w_h (1024 thr each);
// last block does deterministic mask compaction + zeroes split counters.
// ---------------------------------------------------------------------------
__global__ __launch_bounds__(1024)
void prep_kernel(const float4* __restrict__ wu, float4* __restrict__ wu_c,
                 const float4* __restrict__ wh, float4* __restrict__ wh_c,
                 const int* __restrict__ mask) {
    constexpr int N1 = F_ * E_ / 4;     // 262144
    constexpr int N2 = H_ * E_ / 4;     // 131072
    constexpr int NB_CVT = (N1 + N2) / 1024;  // 384

    if (blockIdx.x < NB_CVT) {
        int i = blockIdx.x * 1024 + threadIdx.x;
        const float4* src; float4* dst;
        if (i < N1) { src = wu + i; dst = wu_c + i; }
        else        { src = wh + (i - N1); dst = wh_c + (i - N1); }
        float4 v = *src;
        v.x = __uint_as_float(f2tf32(v.x));
        v.y = __uint_as_float(f2tf32(v.y));
        v.z = __uint_as_float(f2tf32(v.z));
        v.w = __uint_as_float(f2tf32(v.w));
        *dst = v;
        return;
    }

    // --- compaction block ---
    __shared__ int wsum[32];
    __shared__ int s_base;
    const int tid  = threadIdx.x;
    const int lane = tid & 31;
    const int warp = tid >> 5;
    if (tid < 196) g_ctr_uv[tid] = 0;
    if (tid >= 196 && tid < 260) g_ctr_wh[tid - 196] = 0;
    if (tid == 0) s_base = 0;
    __syncthreads();

    for (int base = 0; base < BN_; base += 1024) {
        int i = base + tid;
        int m = (i < BN_) && (mask[i] != 0);
        unsigned bal = __ballot_sync(0xFFFFFFFFu, m);
        int pre = __popc(bal & ((1u << lane) - 1));
        if (lane == 0) wsum[warp] = __popc(bal);
        __syncthreads();
        if (warp == 0) {
            int v = wsum[lane];
            #pragma unroll
            for (int off = 1; off < 32; off <<= 1) {
                int o = __shfl_up_sync(0xFFFFFFFFu, v, off);
                if (lane >= off) v += o;
            }
            wsum[lane] = v;
        }
        __syncthreads();
        int woff = (warp == 0) ? 0 : wsum[warp - 1];
        int pos  = s_base + woff + pre;
        if (i < BN_) {
            if (m) { g_row_list[pos] = i; g_idx_map[i] = pos; }
            else     g_idx_map[i] = -1;
        }
        int total = wsum[31];
        __syncthreads();
        if (tid == 0) s_base += total;
        __syncthreads();
    }
    if (tid == 0) g_nact = s_base;
}

// ---------------------------------------------------------------------------
// Core GEMM tile (r13-proven).
// ---------------------------------------------------------------------------
template<int TBM, int WM, int WN, int THREADS, int STAGES, bool RA, bool RB, bool GATHER>
__device__ __forceinline__
void gemm_core(const float* __restrict__ A, const float* __restrict__ B,
               float* __restrict__ C, int M, int N, int Keff, int lda,
               int row0, int col0, float* smem, const int* __restrict__ rlist) {
    constexpr int TBN = 128;
    constexpr int WARPS_N = TBN / WN;
    constexpr int MI = WM / 16;
    constexpr int NJ = WN / 8;
    constexpr int AR = THREADS / 4;
    constexpr int BR = THREADS / 32;
    constexpr int AQ = TBM / AR;

    float* As = smem;
    float* Bs = smem + STAGES * TBM * PA;

    const int tid    = threadIdx.x;
    const int wid    = tid >> 5;
    const int lane   = tid & 31;
    const int g      = lane >> 2;
    const int t      = lane & 3;
    const int warp_m = wid / WARPS_N;
    const int warp_n = wid % WARPS_N;

    const int a_row = tid >> 2;
    const int a_col = (tid & 3) << 2;
    const int b_row = tid >> 5;
    const int b_col = (tid & 31) << 2;

    int grow[AQ];
    #pragma unroll
    for (int q = 0; q < AQ; q++) {
        int r = row0 + a_row + q * AR;
        grow[q] = (r < M) ? (GATHER ? rlist[r] : r) : 0;
    }

    const int nK = (Keff + BK - 1) / BK;

    float acc[MI][NJ][4] = {};

    auto load_stage = [&](int st, int k0) {
        float* as = As + st * TBM * PA;
        float* bs = Bs + st * BK * PB;
        #pragma unroll
        for (int q = 0; q < AQ; q++) {
            int r = a_row + q * AR;
            int kk = k0 + a_col;
            uint32_t s = (uint32_t)__cvta_generic_to_shared(&as[r * PA + a_col]);
            cp_async16(s, A + (long long)grow[q] * lda + kk,
                       (row0 + r < M) && (kk < Keff));
        }
        #pragma unroll
        for (int br = b_row; br < BK; br += BR) {
            int kk = k0 + br;
            uint32_t s = (uint32_t)__cvta_generic_to_shared(&bs[br * PB + b_col]);
            cp_async16(s, B + (long long)kk * N + col0 + b_col, kk < Keff);
        }
    };

    #pragma unroll
    for (int s = 0; s < STAGES - 1; s++) {
        if (s < nK) load_stage(s, s * BK);
        asm volatile("cp.async.commit_group;");
    }

    for (int it = 0; it < nK; it++) {
        asm volatile("cp.async.wait_group %0;" :: "n"(STAGES - 2));
        __syncthreads();

        int lds = it + STAGES - 1;
        if (lds < nK) load_stage(lds % STAGES, lds * BK);
        asm volatile("cp.async.commit_group;");

        const float* as = As + (it % STAGES) * TBM * PA;
        const float* bs = Bs + (it % STAGES) * BK * PB;

        #pragma unroll
        for (int k8 = 0; k8 < 2; k8++) {
            const int kb = k8 * 8;
            uint32_t af[MI][4], bf[NJ][2];
            #pragma unroll
            for (int i = 0; i < MI; i++) {
                int rb = warp_m * WM + i * 16;
                float a0 = as[(rb + g    ) * PA + kb + t    ];
                float a1 = as[(rb + g + 8) * PA + kb + t    ];
                float a2 = as[(rb + g    ) * PA + kb + t + 4];
                float a3 = as[(rb + g + 8) * PA + kb + t + 4];
                af[i][0] = RA ? f2tf32(a0) : __float_as_uint(a0);
                af[i][1] = RA ? f2tf32(a1) : __float_as_uint(a1);
                af[i][2] = RA ? f2tf32(a2) : __float_as_uint(a2);
                af[i][3] = RA ? f2tf32(a3) : __float_as_uint(a3);
            }
            #pragma unroll
            for (int j = 0; j < NJ; j++) {
                int cb = warp_n * WN + j * 8;
                float b0 = bs[(kb + t    ) * PB + cb + g];
                float b1 = bs[(kb + t + 4) * PB + cb + g];
                bf[j][0] = RB ? f2tf32(b0) : __float_as_uint(b0);
                bf[j][1] = RB ? f2tf32(b1) : __float_as_uint(b1);
            }
            #pragma unroll
            for (int i = 0; i < MI; i++)
                #pragma unroll
                for (int j = 0; j < NJ; j++)
                    mma_tf32(acc[i][j], af[i], bf[j]);
        }
        __syncthreads();
    }

    #pragma unroll
    for (int i = 0; i < MI; i++) {
        #pragma unroll
        for (int j = 0; j < NJ; j++) {
            int r = row0 + warp_m * WM + i * 16 + g;
            int c = col0 + warp_n * WN + j * 8 + 2 * t;
            if (r < M) {
                float2 v0 = make_float2(acc[i][j][0], acc[i][j][1]);
                *reinterpret_cast<float2*>(&C[(long long)r * N + c]) = v0;
            }
            if (r + 8 < M) {
                float2 v1 = make_float2(acc[i][j][2], acc[i][j][3]);
                *reinterpret_cast<float2*>(&C[(long long)(r + 8) * N + c]) = v1;
            }
        }
    }
}

// Last-arriving block reduces its 64x128 tile from NS partials (fixed order).
template<int NS>
__device__ __forceinline__
void tile_reduce(const float* __restrict__ P, long long stride4,
                 float* __restrict__ out, int M, int row0, int col0) {
    const float4* p = reinterpret_cast<const float4*>(P);
    float4* o = reinterpret_cast<float4*>(out);
    int rows = M - row0; if (rows > 64) rows = 64;
    for (int idx = threadIdx.x; idx < rows * 32; idx += 64) {
        int r = idx >> 5, c = idx & 31;
        long long b4 = (((long long)(row0 + r) * E_ + col0) >> 2) + c;
        float4 s0 = p[b4];
        float4 s1 = p[stride4 + b4];
        float4 rr;
        if (NS == 4) {
            float4 s2 = p[2 * stride4 + b4];
            float4 s3 = p[3 * stride4 + b4];
            rr.x = (s0.x + s1.x) + (s2.x + s3.x);
            rr.y = (s0.y + s1.y) + (s2.y + s3.y);
            rr.z = (s0.z + s1.z) + (s2.z + s3.z);
            rr.w = (s0.w + s1.w) + (s2.w + s3.w);
        } else {
            rr.x = s0.x + s1.x; rr.y = s0.y + s1.y;
            rr.z = s0.z + s1.z; rr.w = s0.w + s1.w;
        }
        o[b4] = rr;
    }
}

// ---------------------------------------------------------------------------
// Dual GEMM with inline split-K reduction (last block per tile reduces).
//   blocks [0,128): Wh split-K x2; rest: Uv split-K x4 over compact rows.
// ---------------------------------------------------------------------------
__global__ __launch_bounds__(64)
void gemm_dual_split(const float* __restrict__ hidden, const float* __restrict__ wh_c,
                     const float* __restrict__ feats, const float* __restrict__ wu_c) {
    extern __shared__ float smem[];
    __shared__ int s_last;
    int bx = blockIdx.x;
    constexpr int NB_WH = (BS_ / 64) * 4 * KSPLIT_WH;   // 128
    if (bx < NB_WH) {
        int split  = bx / 64;
        int within = bx % 64;
        int row0   = (within / 4) * 64;
        int col0   = (within % 4) * 128;
        int k0     = split * (H_ / KSPLIT_WH);
        gemm_core<64, 64, 64, 64, STG, true, false, false>(
            hidden + k0, wh_c + (long long)k0 * E_,
            g_WhP[split], BS_, E_, H_ / KSPLIT_WH, H_,
            row0, col0, smem, nullptr);
        __threadfence();
        if (threadIdx.x == 0)
            s_last = (atomicAdd(&g_ctr_wh[within], 1) == KSPLIT_WH - 1);
        __syncthreads();
        if (s_last)
            tile_reduce<KSPLIT_WH>(g_WhP[0], (long long)BS_ * E_ / 4,
                                   g_Wh, BS_, row0, col0);
    } else {
        bx -= NB_WH;
        int split  = bx / 196;
        int within = bx % 196;
        int row0   = (within / 4) * 64;
        int col0   = (within % 4) * 128;
        int M      = g_nact;
        if (row0 >= M) return;              // dead tile (all splits agree)
        int k0     = split * (F_ / KSPLIT);
        gemm_core<64, 64, 64, 64, STG, true, false, true>(
            feats + k0, wu_c + (long long)k0 * E_,
            g_UvP[split], M, E_, F_ / KSPLIT, F_,
            row0, col0, smem, g_row_list);
        __threadfence();
        if (threadIdx.x == 0)
            s_last = (atomicAdd(&g_ctr_uv[within], 1) == KSPLIT - 1);
        __syncthreads();
        if (s_last)
            tile_reduce<KSPLIT>(g_UvP[0], (long long)BN_ * E_ / 4,
                                g_Uv, M, row0, col0);
    }
}

// attn GEMM: batched over b, A = tf32-rounded weights, B = feats (cvt in loop)
__global__ __launch_bounds__(64)
void gemm_attn(const float* __restrict__ A, const float* __restrict__ B,
               float* __restrict__ C) {
    extern __shared__ float smem[];
    gemm_core<64, 64, 64, 64, STG, false, true, false>(
        A + (long long)blockIdx.z * S_ * N_,
        B + (long long)blockIdx.z * N_ * F_,
        C + (long long)blockIdx.z * S_ * F_,
        S_, F_, N_, N_,
        0, blockIdx.x * 128, smem, nullptr);
}

// ---------------------------------------------------------------------------
// Fused scores + mask + softmax (r12/r13-proven), Uv via compact index map.
// ---------------------------------------------------------------------------
#define SG 2

__device__ __forceinline__ float tanh_apx(float x) {
    float r;
    asm("tanh.approx.f32 %0, %1;" : "=f"(r) : "f"(x));
    return r;
}

__global__ __launch_bounds__(256)
void scores_softmax_kernel(const float* __restrict__ Wh,
                           const float* __restrict__ Uv,
                           const float* __restrict__ bias,
                           const float* __restrict__ w,
                           float* __restrict__ weights,
                           float* __restrict__ wts_c) {
    const int blk  = blockIdx.x;
    const int b    = blk / (S_ / SG);
    const int s0   = (blk % (S_ / SG)) * SG;
    const int tid  = threadIdx.x;
    const int warp = tid >> 5;
    const int lane = tid & 31;

    __shared__ float s_sc[SG][N_];
    __shared__ int   s_act[N_];
    __shared__ int   s_uvi[N_];
    __shared__ int   s_nact;

    if (tid == 0) s_nact = 0;
    __syncthreads();

    for (int n = tid; n < N_; n += 256) {
        int gi = g_idx_map[b * N_ + n];
        if (gi >= 0) {
            int p = atomicAdd(&s_nact, 1);
            s_act[p] = n;
            s_uvi[p] = gi;
        } else {
            #pragma unroll
            for (int s = 0; s < SG; s++)
                s_sc[s][n] = -1e9f;
        }
    }

    float4 wf[4], qf[SG][4];
    #pragma unroll
    for (int j = 0; j < 4; j++) {
        wf[j] = reinterpret_cast<const float4*>(w)[j * 32 + lane];
        float4 bf = reinterpret_cast<const float4*>(bias)[j * 32 + lane];
        #pragma unroll
        for (int s = 0; s < SG; s++) {
            float4 q = reinterpret_cast<const float4*>(
                Wh + (long long)(b * S_ + s0 + s) * E_)[j * 32 + lane];
            q.x += bf.x; q.y += bf.y; q.z += bf.z; q.w += bf.w;
            qf[s][j] = q;
        }
    }
    __syncthreads();

    const int nact = s_nact;
    for (int i0 = warp * 2; i0 < nact; i0 += 16) {
        const bool has2 = (i0 + 1 < nact);
        const int n0 = s_act[i0];
        const int n1 = has2 ? s_act[i0 + 1] : n0;
        const int u0i = s_uvi[i0];
        const int u1i = has2 ? s_uvi[i0 + 1] : u0i;

        const float4* uv0 = reinterpret_cast<const float4*>(
            Uv + (long long)u0i * E_);
        const float4* uv1 = reinterpret_cast<const float4*>(
            Uv + (long long)u1i * E_);

        float4 u0[4], u1[4];
        #pragma unroll
        for (int j = 0; j < 4; j++) u0[j] = uv0[j * 32 + lane];
        #pragma unroll
        for (int j = 0; j < 4; j++) u1[j] = uv1[j * 32 + lane];

        float acc0[SG] = {}, acc1[SG] = {};
        #pragma unroll
        for (int j = 0; j < 4; j++) {
            const float uw[2][4] = {{u0[j].x, u0[j].y, u0[j].z, u0[j].w},
                                    {u1[j].x, u1[j].y, u1[j].z, u1[j].w}};
            const float wc[4] = {wf[j].x, wf[j].y, wf[j].z, wf[j].w};
            #pragma unroll
            for (int s = 0; s < SG; s++) {
                const float qc[4] = {qf[s][j].x, qf[s][j].y, qf[s][j].z, qf[s][j].w};
                #pragma unroll
                for (int c = 0; c < 4; c++) {
                    acc0[s] = fmaf(wc[c], tanh_apx(qc[c] + uw[0][c]), acc0[s]);
                    acc1[s] = fmaf(wc[c], tanh_apx(qc[c] + uw[1][c]), acc1[s]);
                }
            }
        }
        #pragma unroll
        for (int s = 0; s < SG; s++) {
            float v0 = acc0[s];
            float v1 = acc1[s];
            #pragma unroll
            for (int off = 16; off; off >>= 1) {
                v0 += __shfl_xor_sync(0xFFFFFFFFu, v0, off);
                v1 += __shfl_xor_sync(0xFFFFFFFFu, v1, off);
            }
            if (lane == 0) {
                s_sc[s][n0] = v0;
                if (has2) s_sc[s][n1] = v1;
            }
        }
    }
    __syncthreads();

    if (warp < SG) {
        const int s = warp;
        float vals[7];
        float mx = -3.4e38f;
        #pragma unroll
        for (int it = 0; it < 7; it++) {
            int n = lane + 32 * it;
            float v = (n < N_) ? s_sc[s][n] : -3.4e38f;
            vals[it] = v;
            mx = fmaxf(mx, v);
        }
        #pragma unroll
        for (int off = 16; off; off >>= 1)
            mx = fmaxf(mx, __shfl_xor_sync(0xFFFFFFFFu, mx, off));

        float sum = 0.f;
        #pragma unroll
        for (int it = 0; it < 7; it++) {
            int n = lane + 32 * it;
            float ev = (n < N_) ? __expf(vals[it] - mx) : 0.f;
            vals[it] = ev;
            sum += ev;
        }
        #pragma unroll
        for (int off = 16; off; off >>= 1)
            sum += __shfl_xor_sync(0xFFFFFFFFu, sum, off);
        float inv = 1.f / sum;

        const long long base = (long long)(b * S_ + s0 + s) * N_;
        #pragma unroll
        for (int it = 0; it < 7; it++) {
            int n = lane + 32 * it;
            if (n < N_) {
                float wv = vals[it] * inv;
                weights[base + n] = wv;
                wts_c[base + n]   = __uint_as_float(f2tf32(wv));
            }
        }
    }
}

// ---------------------------------------------------------------------------
// Launch
// ---------------------------------------------------------------------------
extern "C" void kernel_launch(void* const* d_in, const int* in_sizes, int n_in,
                              void* d_out, int out_size) {
    const float* hidden = (const float*)d_in[0];   // [16,64,1024]
    const float* feats  = (const float*)d_in[1];   // [16,196,2048]
    const int*   amask  = (const int*)  d_in[2];   // [16,196]
    const float* w_h    = (const float*)d_in[3];   // [1024,512]
    const float* w_u    = (const float*)d_in[4];   // [2048,512]
    const float* bias   = (const float*)d_in[5];   // [512]
    const float* w      = (const float*)d_in[6];   // [512]

    float* out_attn = (float*)d_out;               // [1024, 2048]
    float* out_wts  = (float*)d_out + ATTN_ELEMS;  // [1024, 196]

    float *Wh, *Uv, *wu_c, *wh_c, *wts_c;
    cudaGetSymbolAddress((void**)&Wh,    g_Wh);
    cudaGetSymbolAddress((void**)&Uv,    g_Uv);
    cudaGetSymbolAddress((void**)&wu_c,  g_wu_c);
    cudaGetSymbolAddress((void**)&wh_c,  g_wh_c);
    cudaGetSymbolAddress((void**)&wts_c, g_wts_c);

    constexpr int SMEM = STG * (64 * PA + BK * PB) * 4;  // 54272 B

    cudaFuncSetAttribute(gemm_dual_split,
                         cudaFuncAttributeMaxDynamicSharedMemorySize, SMEM);
    cudaFuncSetAttribute(gemm_attn,
                         cudaFuncAttributeMaxDynamicSharedMemorySize, SMEM);

    // 0) fused: tf32 pre-round (384 blocks) + compaction/counter-reset (1 block)
    {
        constexpr int NB = (F_ * E_ + H_ * E_) / 4 / 1024 + 1;  // 385
        prep_kernel<<<NB, 1024>>>((const float4*)w_u, (float4*)wu_c,
                                  (const float4*)w_h, (float4*)wh_c, amask);
    }
    // 1) dual GEMM with inline split-K reduce (last block per tile)
    {
        int nb = (BS_ / 64) * 4 * KSPLIT_WH + 196 * KSPLIT;   // 912
        gemm_dual_split<<<nb, 64, SMEM>>>(hidden, wh_c, feats, wu_c);
    }
    // 2) fused scores + mask + softmax -> weights (+ tf32 shadow)
    scores_softmax_kernel<<<B_ * (S_ / SG), 256>>>(Wh, Uv, bias, w,
                                                   out_wts, wts_c);
    // 3) attn_feats[b] = weights[b] @ feats[b]
    {
        dim3 grid(F_ / 128, 1, B_);
        gemm_attn<<<grid, 64, SMEM>>>(wts_c, feats, out_attn);
    }
}

// round 16
// speedup vs baseline: 1.1045x; 1.1045x over previous
#include <cuda_runtime.h>
#include <cuda_bf16.h>
#include <cstdint>

// Problem constants
#define B_  16
#define S_  64
#define N_  196
#define H_  1024
#define F_  2048
#define E_  512

#define BS_ (B_ * S_)           // 1024
#define BN_ (B_ * N_)           // 3136 = 49*64
#define ATTN_ELEMS (BS_ * F_)   // attn_feats first in d_out

#define KSPLIT 4                // Uv split-K factor
#define KSPLIT_WH 2             // Wh split-K factor
#define LDW 196                 // compact weights row stride (196*4=784, 16B-aligned)

// Scratch (__device__ globals; allocation-free rule)
__device__ float g_Wh[BS_ * E_];                 // reduced Wh
__device__ float g_Uv[BN_ * E_];                 // reduced Uv (compact rows)
__device__ float g_UvP[KSPLIT][BN_ * E_];        // Uv split-K partials
__device__ float g_WhP[KSPLIT_WH][BS_ * E_];     // Wh split-K partials
__device__ float g_wu_c[F_ * E_];                // tf32-rounded w_u
__device__ float g_wh_c[H_ * E_];                // tf32-rounded w_h
__device__ float g_wts_lc[BS_ * LDW];            // compact tf32 weights [s][local act]
__device__ int   g_row_list[BN_];                // compact idx -> global row
__device__ int   g_idx_map[BN_];                 // global row -> compact idx / -1
__device__ int   g_batch_start[B_ + 1];          // per-batch compact offsets
__device__ int   g_nact;                         // total active rows

#define BK 16
#define PA 20
#define PB 132
#define STG 4

__device__ __forceinline__ uint32_t f2tf32(float f) {
    uint32_t u;
    asm("cvt.rna.tf32.f32 %0, %1;" : "=r"(u) : "f"(f));
    return u;
}

__device__ __forceinline__ void mma_tf32(float* c, const uint32_t* a, const uint32_t* b) {
    asm volatile(
        "mma.sync.aligned.m16n8k8.row.col.f32.tf32.tf32.f32 "
        "{%0,%1,%2,%3}, {%4,%5,%6,%7}, {%8,%9}, {%0,%1,%2,%3};"
        : "+f"(c[0]), "+f"(c[1]), "+f"(c[2]), "+f"(c[3])
        : "r"(a[0]), "r"(a[1]), "r"(a[2]), "r"(a[3]), "r"(b[0]), "r"(b[1]));
}

__device__ __forceinline__ void cp_async16(uint32_t smem, const void* gmem, bool pred) {
    int sz = pred ? 16 : 0;
    asm volatile("cp.async.cg.shared.global [%0], [%1], 16, %2;"
                 :: "r"(smem), "l"(gmem), "r"(sz));
}

// ---------------------------------------------------------------------------
// Fused prep: blocks [0,384) tf32-round w_u|w_h; last block compacts mask
// (deterministic ballot scan) and computes per-batch offsets.
// ---------------------------------------------------------------------------
__global__ __launch_bounds__(1024)
void prep_kernel(const float4* __restrict__ wu, float4* __restrict__ wu_c,
                 const float4* __restrict__ wh, float4* __restrict__ wh_c,
                 const int* __restrict__ mask) {
    constexpr int N1 = F_ * E_ / 4;
    constexpr int N2 = H_ * E_ / 4;
    constexpr int NB_CVT = (N1 + N2) / 1024;  // 384

    if (blockIdx.x < NB_CVT) {
        int i = blockIdx.x * 1024 + threadIdx.x;
        const float4* src; float4* dst;
        if (i < N1) { src = wu + i; dst = wu_c + i; }
        else        { src = wh + (i - N1); dst = wh_c + (i - N1); }
        float4 v = *src;
        v.x = __uint_as_float(f2tf32(v.x));
        v.y = __uint_as_float(f2tf32(v.y));
        v.z = __uint_as_float(f2tf32(v.z));
        v.w = __uint_as_float(f2tf32(v.w));
        *dst = v;
        return;
    }

    // --- compaction block ---
    __shared__ int wsum[32];
    __shared__ int bcnt[B_];
    __shared__ int s_base;
    const int tid  = threadIdx.x;
    const int lane = tid & 31;
    const int warp = tid >> 5;

    if (tid < B_) {
        int c = 0;
        for (int n = 0; n < N_; n++) c += (mask[tid * N_ + n] != 0);
        bcnt[tid] = c;
    }
    if (tid == 0) s_base = 0;
    __syncthreads();
    if (tid == 0) {
        int acc = 0;
        for (int b = 0; b < B_; b++) { g_batch_start[b] = acc; acc += bcnt[b]; }
        g_batch_start[B_] = acc;
    }

    for (int base = 0; base < BN_; base += 1024) {
        int i = base + tid;
        int m = (i < BN_) && (mask[i] != 0);
        unsigned bal = __ballot_sync(0xFFFFFFFFu, m);
        int pre = __popc(bal & ((1u << lane) - 1));
        if (lane == 0) wsum[warp] = __popc(bal);
        __syncthreads();
        if (warp == 0) {
            int v = wsum[lane];
            #pragma unroll
            for (int off = 1; off < 32; off <<= 1) {
                int o = __shfl_up_sync(0xFFFFFFFFu, v, off);
                if (lane >= off) v += o;
            }
            wsum[lane] = v;
        }
        __syncthreads();
        int woff = (warp == 0) ? 0 : wsum[warp - 1];
        int pos  = s_base + woff + pre;
        if (i < BN_) {
            if (m) { g_row_list[pos] = i; g_idx_map[i] = pos; }
            else     g_idx_map[i] = -1;
        }
        int total = wsum[31];
        __syncthreads();
        if (tid == 0) s_base += total;
        __syncthreads();
    }
    if (tid == 0) g_nact = s_base;
}

// ---------------------------------------------------------------------------
// Core GEMM tile. GA: gather A rows via rlist. GB: gather B rows via rlistB.
// ---------------------------------------------------------------------------
template<int TBM, int WM, int WN, int THREADS, int STAGES,
         bool RA, bool RB, bool GA, bool GB>
__device__ __forceinline__
void gemm_core(const float* __restrict__ A, const float* __restrict__ B,
               float* __restrict__ C, int M, int N, int Keff, int lda,
               int row0, int col0, float* smem,
               const int* __restrict__ rlist, const int* __restrict__ rlistB) {
    constexpr int TBN = 128;
    constexpr int WARPS_N = TBN / WN;
    constexpr int MI = WM / 16;
    constexpr int NJ = WN / 8;
    constexpr int AR = THREADS / 4;
    constexpr int BR = THREADS / 32;
    constexpr int AQ = TBM / AR;

    float* As = smem;
    float* Bs = smem + STAGES * TBM * PA;

    const int tid    = threadIdx.x;
    const int wid    = tid >> 5;
    const int lane   = tid & 31;
    const int g      = lane >> 2;
    const int t      = lane & 3;
    const int warp_m = wid / WARPS_N;
    const int warp_n = wid % WARPS_N;

    const int a_row = tid >> 2;
    const int a_col = (tid & 3) << 2;
    const int b_row = tid >> 5;
    const int b_col = (tid & 31) << 2;

    int grow[AQ];
    #pragma unroll
    for (int q = 0; q < AQ; q++) {
        int r = row0 + a_row + q * AR;
        grow[q] = (r < M) ? (GA ? rlist[r] : r) : 0;
    }

    const int nK = (Keff + BK - 1) / BK;

    float acc[MI][NJ][4] = {};

    auto load_stage = [&](int st, int k0) {
        float* as = As + st * TBM * PA;
        float* bs = Bs + st * BK * PB;
        #pragma unroll
        for (int q = 0; q < AQ; q++) {
            int r = a_row + q * AR;
            int kk = k0 + a_col;
            uint32_t s = (uint32_t)__cvta_generic_to_shared(&as[r * PA + a_col]);
            cp_async16(s, A + (long long)grow[q] * lda + kk,
                       (row0 + r < M) && (kk < Keff));
        }
        #pragma unroll
        for (int br = b_row; br < BK; br += BR) {
            int kk = k0 + br;
            int brow = kk;
            if (GB) brow = (kk < Keff) ? rlistB[kk] : 0;
            uint32_t s = (uint32_t)__cvta_generic_to_shared(&bs[br * PB + b_col]);
            cp_async16(s, B + (long long)brow * N + col0 + b_col, kk < Keff);
        }
    };

    #pragma unroll
    for (int s = 0; s < STAGES - 1; s++) {
        if (s < nK) load_stage(s, s * BK);
        asm volatile("cp.async.commit_group;");
    }

    for (int it = 0; it < nK; it++) {
        asm volatile("cp.async.wait_group %0;" :: "n"(STAGES - 2));
        __syncthreads();

        int lds = it + STAGES - 1;
        if (lds < nK) load_stage(lds % STAGES, lds * BK);
        asm volatile("cp.async.commit_group;");

        const float* as = As + (it % STAGES) * TBM * PA;
        const float* bs = Bs + (it % STAGES) * BK * PB;

        #pragma unroll
        for (int k8 = 0; k8 < 2; k8++) {
            const int kb = k8 * 8;
            uint32_t af[MI][4], bf[NJ][2];
            #pragma unroll
            for (int i = 0; i < MI; i++) {
                int rb = warp_m * WM + i * 16;
                float a0 = as[(rb + g    ) * PA + kb + t    ];
                float a1 = as[(rb + g + 8) * PA + kb + t    ];
                float a2 = as[(rb + g    ) * PA + kb + t + 4];
                float a3 = as[(rb + g + 8) * PA + kb + t + 4];
                af[i][0] = RA ? f2tf32(a0) : __float_as_uint(a0);
                af[i][1] = RA ? f2tf32(a1) : __float_as_uint(a1);
                af[i][2] = RA ? f2tf32(a2) : __float_as_uint(a2);
                af[i][3] = RA ? f2tf32(a3) : __float_as_uint(a3);
            }
            #pragma unroll
            for (int j = 0; j < NJ; j++) {
                int cb = warp_n * WN + j * 8;
                float b0 = bs[(kb + t    ) * PB + cb + g];
                float b1 = bs[(kb + t + 4) * PB + cb + g];
                bf[j][0] = RB ? f2tf32(b0) : __float_as_uint(b0);
                bf[j][1] = RB ? f2tf32(b1) : __float_as_uint(b1);
            }
            #pragma unroll
            for (int i = 0; i < MI; i++)
                #pragma unroll
                for (int j = 0; j < NJ; j++)
                    mma_tf32(acc[i][j], af[i], bf[j]);
        }
        __syncthreads();
    }

    #pragma unroll
    for (int i = 0; i < MI; i++) {
        #pragma unroll
        for (int j = 0; j < NJ; j++) {
            int r = row0 + warp_m * WM + i * 16 + g;
            int c = col0 + warp_n * WN + j * 8 + 2 * t;
            if (r < M) {
                float2 v0 = make_float2(acc[i][j][0], acc[i][j][1]);
                *reinterpret_cast<float2*>(&C[(long long)r * N + c]) = v0;
            }
            if (r + 8 < M) {
                float2 v1 = make_float2(acc[i][j][2], acc[i][j][3]);
                *reinterpret_cast<float2*>(&C[(long long)(r + 8) * N + c]) = v1;
            }
        }
    }
}

// ---------------------------------------------------------------------------
// Dual GEMM (r14-proven): Wh split-K x2 (128 blocks) + Uv split-K x4.
// ---------------------------------------------------------------------------
__global__ __launch_bounds__(64)
void gemm_dual_split(const float* __restrict__ hidden, const float* __restrict__ wh_c,
                     float* __restrict__ WhP,
                     const float* __restrict__ feats, const float* __restrict__ wu_c,
                     float* __restrict__ UvP) {
    extern __shared__ float smem[];
    int bx = blockIdx.x;
    constexpr int NB_WH = (BS_ / 64) * 4 * KSPLIT_WH;   // 128
    if (bx < NB_WH) {
        int split  = bx / 64;
        int within = bx % 64;
        int k0     = split * (H_ / KSPLIT_WH);
        gemm_core<64, 64, 64, 64, STG, true, false, false, false>(
            hidden + k0, wh_c + (long long)k0 * E_,
            WhP + (long long)split * BS_ * E_,
            BS_, E_, H_ / KSPLIT_WH, H_,
            (within / 4) * 64, (within % 4) * 128, smem, nullptr, nullptr);
    } else {
        bx -= NB_WH;
        int split  = bx / 196;
        int within = bx % 196;
        int row0   = (within / 4) * 64;
        int M      = g_nact;
        if (row0 >= M) return;
        int k0     = split * (F_ / KSPLIT);
        gemm_core<64, 64, 64, 64, STG, true, false, true, false>(
            feats + k0, wu_c + (long long)k0 * E_,
            UvP + (long long)split * BN_ * E_,
            M, E_, F_ / KSPLIT, F_,
            row0, (within % 4) * 128, smem, g_row_list, nullptr);
    }
}

// ---------------------------------------------------------------------------
// Merged split-K reduce (r14-proven): Uv (4 partials) then Wh (2 partials).
// ---------------------------------------------------------------------------
__global__ __launch_bounds__(256)
void reduce_kernel(const float4* __restrict__ pu, float4* __restrict__ uv,
                   const float4* __restrict__ pw, float4* __restrict__ wh) {
    constexpr int N4U = BN_ * E_ / 4;
    constexpr int N4W = BS_ * E_ / 4;
    int bound_uv = g_nact * (E_ / 4);
    int i = blockIdx.x * 256 + threadIdx.x;
    if (i < bound_uv) {
        float4 a = pu[i];
        float4 b = pu[N4U + i];
        float4 c = pu[2 * N4U + i];
        float4 d = pu[3 * N4U + i];
        float4 r;
        r.x = (a.x + b.x) + (c.x + d.x);
        r.y = (a.y + b.y) + (c.y + d.y);
        r.z = (a.z + b.z) + (c.z + d.z);
        r.w = (a.w + b.w) + (c.w + d.w);
        uv[i] = r;
    } else {
        int j = i - bound_uv;
        if (j >= N4W) return;
        float4 a = pw[j];
        float4 b = pw[N4W + j];
        float4 r;
        r.x = a.x + b.x; r.y = a.y + b.y;
        r.z = a.z + b.z; r.w = a.w + b.w;
        wh[j] = r;
    }
}

// ---------------------------------------------------------------------------
// attn GEMM over ACTIVE n only: A = compact tf32 weights [64, nact_b]
// (lda=LDW), B = feats rows gathered via g_row_list. 128 threads, 32x64 warps.
// ---------------------------------------------------------------------------
__global__ __launch_bounds__(128)
void gemm_attn(const float* __restrict__ Wl, const float* __restrict__ feats,
               float* __restrict__ C) {
    extern __shared__ float smem[];
    int b = blockIdx.z;
    int start = g_batch_start[b];
    int Keff  = g_batch_start[b + 1] - start;
    gemm_core<64, 32, 64, 128, STG, false, true, false, true>(
        Wl + (long long)b * S_ * LDW, feats,
        C + (long long)b * S_ * F_,
        S_, F_, Keff, LDW,
        0, blockIdx.x * 128, smem, nullptr, g_row_list + start);
}

// ---------------------------------------------------------------------------
// Fused scores + mask + softmax; writes full weights + COMPACT tf32 weights.
// ---------------------------------------------------------------------------
#define SG 2

__device__ __forceinline__ float tanh_apx(float x) {
    float r;
    asm("tanh.approx.f32 %0, %1;" : "=f"(r) : "f"(x));
    return r;
}

__global__ __launch_bounds__(256)
void scores_softmax_kernel(const float* __restrict__ Wh,
                           const float* __restrict__ Uv,
                           const float* __restrict__ bias,
                           const float* __restrict__ w,
                           float* __restrict__ weights,
                           float* __restrict__ wts_lc) {
    const int blk  = blockIdx.x;
    const int b    = blk / (S_ / SG);
    const int s0   = (blk % (S_ / SG)) * SG;
    const int tid  = threadIdx.x;
    const int warp = tid >> 5;
    const int lane = tid & 31;

    __shared__ float s_sc[SG][N_];
    __shared__ int   s_act[N_];
    __shared__ int   s_uvi[N_];
    __shared__ int   s_gi[N_];
    __shared__ int   s_nact;

    if (tid == 0) s_nact = 0;
    __syncthreads();

    for (int n = tid; n < N_; n += 256) {
        int gi = g_idx_map[b * N_ + n];
        s_gi[n] = gi;
        if (gi >= 0) {
            int p = atomicAdd(&s_nact, 1);
            s_act[p] = n;
            s_uvi[p] = gi;
        } else {
            #pragma unroll
            for (int s = 0; s < SG; s++)
                s_sc[s][n] = -1e9f;
        }
    }

    float4 wf[4], qf[SG][4];
    #pragma unroll
    for (int j = 0; j < 4; j++) {
        wf[j] = reinterpret_cast<const float4*>(w)[j * 32 + lane];
        float4 bf = reinterpret_cast<const float4*>(bias)[j * 32 + lane];
        #pragma unroll
        for (int s = 0; s < SG; s++) {
            float4 q = reinterpret_cast<const float4*>(
                Wh + (long long)(b * S_ + s0 + s) * E_)[j * 32 + lane];
            q.x += bf.x; q.y += bf.y; q.z += bf.z; q.w += bf.w;
            qf[s][j] = q;
        }
    }
    __syncthreads();

    const int nact = s_nact;
    for (int i0 = warp * 2; i0 < nact; i0 += 16) {
        const bool has2 = (i0 + 1 < nact);
        const int n0 = s_act[i0];
        const int n1 = has2 ? s_act[i0 + 1] : n0;
        const int u0i = s_uvi[i0];
        const int u1i = has2 ? s_uvi[i0 + 1] : u0i;

        const float4* uv0 = reinterpret_cast<const float4*>(
            Uv + (long long)u0i * E_);
        const float4* uv1 = reinterpret_cast<const float4*>(
            Uv + (long long)u1i * E_);

        float4 u0[4], u1[4];
        #pragma unroll
        for (int j = 0; j < 4; j++) u0[j] = uv0[j * 32 + lane];
        #pragma unroll
        for (int j = 0; j < 4; j++) u1[j] = uv1[j * 32 + lane];

        float acc0[SG] = {}, acc1[SG] = {};
        #pragma unroll
        for (int j = 0; j < 4; j++) {
            const float uw[2][4] = {{u0[j].x, u0[j].y, u0[j].z, u0[j].w},
                                    {u1[j].x, u1[j].y, u1[j].z, u1[j].w}};
            const float wc[4] = {wf[j].x, wf[j].y, wf[j].z, wf[j].w};
            #pragma unroll
            for (int s = 0; s < SG; s++) {
                const float qc[4] = {qf[s][j].x, qf[s][j].y, qf[s][j].z, qf[s][j].w};
                #pragma unroll
                for (int c = 0; c < 4; c++) {
                    acc0[s] = fmaf(wc[c], tanh_apx(qc[c] + uw[0][c]), acc0[s]);
                    acc1[s] = fmaf(wc[c], tanh_apx(qc[c] + uw[1][c]), acc1[s]);
                }
            }
        }
        #pragma unroll
        for (int s = 0; s < SG; s++) {
            float v0 = acc0[s];
            float v1 = acc1[s];
            #pragma unroll
            for (int off = 16; off; off >>= 1) {
                v0 += __shfl_xor_sync(0xFFFFFFFFu, v0, off);
                v1 += __shfl_xor_sync(0xFFFFFFFFu, v1, off);
            }
            if (lane == 0) {
                s_sc[s][n0] = v0;
                if (has2) s_sc[s][n1] = v1;
            }
        }
    }
    __syncthreads();

    if (warp < SG) {
        const int s = warp;
        const int start_b = g_batch_start[b];
        float vals[7];
        float mx = -3.4e38f;
        #pragma unroll
        for (int it = 0; it < 7; it++) {
            int n = lane + 32 * it;
            float v = (n < N_) ? s_sc[s][n] : -3.4e38f;
            vals[it] = v;
            mx = fmaxf(mx, v);
        }
        #pragma unroll
        for (int off = 16; off; off >>= 1)
            mx = fmaxf(mx, __shfl_xor_sync(0xFFFFFFFFu, mx, off));

        float sum = 0.f;
        #pragma unroll
        for (int it = 0; it < 7; it++) {
            int n = lane + 32 * it;
            float ev = (n < N_) ? __expf(vals[it] - mx) : 0.f;
            vals[it] = ev;
            sum += ev;
        }
        #pragma unroll
        for (int off = 16; off; off >>= 1)
            sum += __shfl_xor_sync(0xFFFFFFFFu, sum, off);
        float inv = 1.f / sum;

        const long long base = (long long)(b * S_ + s0 + s) * N_;
        const long long cbase = (long long)(b * S_ + s0 + s) * LDW;
        #pragma unroll
        for (int it = 0; it < 7; it++) {
            int n = lane + 32 * it;
            if (n < N_) {
                float wv = vals[it] * inv;
                weights[base + n] = wv;
                int gi = s_gi[n];
                if (gi >= 0)
                    wts_lc[cbase + (gi - start_b)] = __uint_as_float(f2tf32(wv));
            }
        }
    }
}

// ---------------------------------------------------------------------------
// Launch
// ---------------------------------------------------------------------------
extern "C" void kernel_launch(void* const* d_in, const int* in_sizes, int n_in,
                              void* d_out, int out_size) {
    const float* hidden = (const float*)d_in[0];   // [16,64,1024]
    const float* feats  = (const float*)d_in[1];   // [16,196,2048]
    const int*   amask  = (const int*)  d_in[2];   // [16,196]
    const float* w_h    = (const float*)d_in[3];   // [1024,512]
    const float* w_u    = (const float*)d_in[4];   // [2048,512]
    const float* bias   = (const float*)d_in[5];   // [512]
    const float* w      = (const float*)d_in[6];   // [512]

    float* out_attn = (float*)d_out;               // [1024, 2048]
    float* out_wts  = (float*)d_out + ATTN_ELEMS;  // [1024, 196]

    float *Wh, *Uv, *UvP, *WhP, *wu_c, *wh_c, *wts_lc;
    cudaGetSymbolAddress((void**)&Wh,     g_Wh);
    cudaGetSymbolAddress((void**)&Uv,     g_Uv);
    cudaGetSymbolAddress((void**)&UvP,    g_UvP);
    cudaGetSymbolAddress((void**)&WhP,    g_WhP);
    cudaGetSymbolAddress((void**)&wu_c,   g_wu_c);
    cudaGetSymbolAddress((void**)&wh_c,   g_wh_c);
    cudaGetSymbolAddress((void**)&wts_lc, g_wts_lc);

    constexpr int SMEM = STG * (64 * PA + BK * PB) * 4;  // 54272 B

    cudaFuncSetAttribute(gemm_dual_split,
                         cudaFuncAttributeMaxDynamicSharedMemorySize, SMEM);
    cudaFuncSetAttribute(gemm_attn,
                         cudaFuncAttributeMaxDynamicSharedMemorySize, SMEM);

    // 0) fused: tf32 pre-round + compaction + batch offsets
    {
        constexpr int NB = (F_ * E_ + H_ * E_) / 4 / 1024 + 1;  // 385
        prep_kernel<<<NB, 1024>>>((const float4*)w_u, (float4*)wu_c,
                                  (const float4*)w_h, (float4*)wh_c, amask);
    }
    // 1) dual GEMM: Wh split-K x2 + Uv split-K x4 over compact rows
    {
        int nb = (BS_ / 64) * 4 * KSPLIT_WH + 196 * KSPLIT;   // 912
        gemm_dual_split<<<nb, 64, SMEM>>>(hidden, wh_c, WhP, feats, wu_c, UvP);
    }
    // 2) merged reduce: Uv (4 partials) + Wh (2 partials)
    {
        constexpr int MAXB = (BN_ * E_ / 4 + BS_ * E_ / 4 + 255) / 256;
        reduce_kernel<<<MAXB, 256>>>((const float4*)UvP, (float4*)Uv,
                                     (const float4*)WhP, (float4*)Wh);
    }
    // 3) fused scores + mask + softmax -> weights (+ compact tf32 weights)
    scores_softmax_kernel<<<B_ * (S_ / SG), 256>>>(Wh, Uv, bias, w,
                                                   out_wts, wts_lc);
    // 4) attn over active n only (gathered feats rows)
    {
        dim3 grid(F_ / 128, 1, B_);
        gemm_attn<<<grid, 128, SMEM>>>(wts_lc, feats, out_attn);
    }
}